// round 1
// baseline (speedup 1.0000x reference)
#include <cuda_runtime.h>

// Problem constants
#define CH   64
#define HH   112
#define WW   112
#define HWS  12544        // 112*112
#define BB   4
#define KK   49           // 7*7
#define NPIX (BB*HWS)     // 50176 samples per channel for BN

// Scratch (device globals: no allocation allowed)
__device__ __align__(16) float g_y0  [BB*CH*HWS];   // reduce output (pre-BN)
__device__ __align__(16) float g_kern[BB*KK*HWS];   // per-pixel kernels
__device__ __align__(16) float g_out0[BB*CH*HWS];   // involution output (pre-BN2)
__device__ float g_stats1[2*CH];                    // sum, sumsq of y0 per channel
__device__ float g_stats2[2*CH];                    // sum, sumsq of out0 per channel
__device__ float g_bn1[2*CH];                       // scale, shift
__device__ float g_bn2[2*CH];                       // scale, shift

// ---------------------------------------------------------------- K0: zero stats
__global__ void k_zero() {
    int t = threadIdx.x;
    if (t < 2*CH) { g_stats1[t] = 0.f; g_stats2[t] = 0.f; }
}

// ---------------------------------------------------------------- K1: reduce GEMM + stats
// y0[b,o,p] = sum_c wred[o,c] * x[b,c,p].  Block: 128 pixels, 128 threads.
// Thread tile: 16 output channels x 4 pixels.
__global__ __launch_bounds__(128) void k_reduce(const float* __restrict__ x,
                                                const float* __restrict__ wred) {
    __shared__ __align__(16) float xs[CH][128];
    __shared__ float ws[CH][CH];        // ws[o][c]
    const int t = threadIdx.x;
    const int b = blockIdx.y;
    const int pix0 = blockIdx.x * 128;

    const float* xb = x + (size_t)b*CH*HWS + pix0;
    #pragma unroll 4
    for (int c = 0; c < CH; c++) xs[c][t] = xb[c*HWS + t];
    for (int i = t; i < CH*CH; i += 128) ws[i >> 6][i & 63] = wred[i];
    __syncthreads();

    const int og = t >> 5;       // warp id: 4 groups of 16 output channels
    const int pg = t & 31;       // pixel group of 4
    float acc[16][4];
    #pragma unroll
    for (int i = 0; i < 16; i++)
        #pragma unroll
        for (int j = 0; j < 4; j++) acc[i][j] = 0.f;

    #pragma unroll 4
    for (int c = 0; c < CH; c++) {
        float4 xv = ((const float4*)xs[c])[pg];
        #pragma unroll
        for (int i = 0; i < 16; i++) {
            float w = ws[og*16 + i][c];
            acc[i][0] = fmaf(w, xv.x, acc[i][0]);
            acc[i][1] = fmaf(w, xv.y, acc[i][1]);
            acc[i][2] = fmaf(w, xv.z, acc[i][2]);
            acc[i][3] = fmaf(w, xv.w, acc[i][3]);
        }
    }

    float* y0b = g_y0 + (size_t)b*CH*HWS + pix0;
    #pragma unroll
    for (int i = 0; i < 16; i++) {
        const int o = og*16 + i;
        float4 v; v.x = acc[i][0]; v.y = acc[i][1]; v.z = acc[i][2]; v.w = acc[i][3];
        ((float4*)(y0b + (size_t)o*HWS))[pg] = v;
        float s = v.x + v.y + v.z + v.w;
        float q = v.x*v.x + v.y*v.y + v.z*v.z + v.w*v.w;
        #pragma unroll
        for (int off = 16; off; off >>= 1) {
            s += __shfl_down_sync(0xffffffffu, s, off);
            q += __shfl_down_sync(0xffffffffu, q, off);
        }
        if (pg == 0) {
            atomicAdd(&g_stats1[o], s);
            atomicAdd(&g_stats1[CH + o], q);
        }
    }
}

// ---------------------------------------------------------------- K2: finalize bn1
__global__ void k_bn1(const float* __restrict__ gamma, const float* __restrict__ beta) {
    int c = threadIdx.x;
    if (c >= CH) return;
    const float n = (float)NPIX;
    float mean = g_stats1[c] / n;
    float var  = g_stats1[CH + c] / n - mean*mean;
    float sc = gamma[c] * rsqrtf(var + 1e-5f);
    g_bn1[c]      = sc;
    g_bn1[CH + c] = beta[c] - mean*sc;
}

// ---------------------------------------------------------------- K3: span GEMM
// kern[b,p,pix] = sum_c wspan[p,c] * relu(bn1(y0[b,c,pix])).  Block: 128 pixels, 224 threads.
// Thread tile: 7 outputs x 4 pixels.
__global__ __launch_bounds__(224) void k_span(const float* __restrict__ wspan) {
    __shared__ __align__(16) float ys[CH][128];
    __shared__ float ws[KK][CH];
    const int t = threadIdx.x;
    const int b = blockIdx.y;
    const int pix0 = blockIdx.x * 128;

    const float* y0b = g_y0 + (size_t)b*CH*HWS + pix0;
    for (int l = t; l < CH*128; l += 224) {
        int c = l >> 7, p = l & 127;
        float v = y0b[(size_t)c*HWS + p];
        v = fmaxf(fmaf(v, g_bn1[c], g_bn1[CH + c]), 0.f);
        ys[c][p] = v;
    }
    for (int l = t; l < KK*CH; l += 224) ws[l >> 6][l & 63] = wspan[l];
    __syncthreads();

    const int og = t >> 5;   // 0..6
    const int pg = t & 31;
    float acc[7][4];
    #pragma unroll
    for (int i = 0; i < 7; i++)
        #pragma unroll
        for (int j = 0; j < 4; j++) acc[i][j] = 0.f;

    #pragma unroll 4
    for (int c = 0; c < CH; c++) {
        float4 xv = ((const float4*)ys[c])[pg];
        #pragma unroll
        for (int i = 0; i < 7; i++) {
            float w = ws[og*7 + i][c];
            acc[i][0] = fmaf(w, xv.x, acc[i][0]);
            acc[i][1] = fmaf(w, xv.y, acc[i][1]);
            acc[i][2] = fmaf(w, xv.z, acc[i][2]);
            acc[i][3] = fmaf(w, xv.w, acc[i][3]);
        }
    }

    float* kb = g_kern + (size_t)b*KK*HWS + pix0;
    #pragma unroll
    for (int i = 0; i < 7; i++) {
        float4 v; v.x = acc[i][0]; v.y = acc[i][1]; v.z = acc[i][2]; v.w = acc[i][3];
        ((float4*)(kb + (size_t)(og*7 + i)*HWS))[pg] = v;
    }
}

// ---------------------------------------------------------------- K4: involution + stats
// out0[b,c,h,w] = sum_{kh,kw} x[b,c,h+kh-3,w+kw-3] * kern[b,kh*7+kw,h,w]
// Block per (h, b), 224 threads: 28 w-groups (4 wide) x 8 channel-lanes (8 ch each).
__global__ __launch_bounds__(224) void k_invol(const float* __restrict__ x) {
    __shared__ __align__(16) float ks[KK][WW];
    __shared__ float sred[2*CH];
    const int t = threadIdx.x;
    const int h = blockIdx.x;
    const int b = blockIdx.y;

    const float* kb = g_kern + (size_t)b*KK*HWS + h*WW;
    for (int l = t; l < KK*WW; l += 224) {
        int p = l / WW, w = l % WW;
        ks[p][w] = kb[(size_t)p*HWS + w];
    }
    if (t < 2*CH) sred[t] = 0.f;
    __syncthreads();

    const int wg = t % 28;          // w-group
    const int cl = t / 28;          // channel lane: channels cl*8 .. cl*8+7
    const int w0 = wg * 4;

    float acc[8][4];
    #pragma unroll
    for (int cc = 0; cc < 8; cc++)
        #pragma unroll
        for (int j = 0; j < 4; j++) acc[cc][j] = 0.f;

    #pragma unroll
    for (int kh = 0; kh < 7; kh++) {
        const int row = h + kh - 3;
        if (row < 0 || row >= HH) continue;
        float kv[7][4];
        #pragma unroll
        for (int kw = 0; kw < 7; kw++) {
            float4 v = ((const float4*)ks[kh*7 + kw])[wg];
            kv[kw][0] = v.x; kv[kw][1] = v.y; kv[kw][2] = v.z; kv[kw][3] = v.w;
        }
        const float* xrow = x + (((size_t)b*CH + cl*8)*HH + row)*WW;
        #pragma unroll
        for (int cc = 0; cc < 8; cc++) {
            float xr[10];
            #pragma unroll
            for (int i = 0; i < 10; i++) {
                int ww = w0 - 3 + i;
                xr[i] = (ww >= 0 && ww < WW) ? xrow[(size_t)cc*HWS + ww] : 0.f;
            }
            #pragma unroll
            for (int j = 0; j < 4; j++)
                #pragma unroll
                for (int kw = 0; kw < 7; kw++)
                    acc[cc][j] = fmaf(xr[j + kw], kv[kw][j], acc[cc][j]);
        }
    }

    float* ob = g_out0 + ((size_t)b*CH + cl*8)*HWS + h*WW + w0;
    #pragma unroll
    for (int cc = 0; cc < 8; cc++) {
        float4 v; v.x = acc[cc][0]; v.y = acc[cc][1]; v.z = acc[cc][2]; v.w = acc[cc][3];
        ((float4*)(ob + (size_t)cc*HWS))[0] = v;
        float s = v.x + v.y + v.z + v.w;
        float q = v.x*v.x + v.y*v.y + v.z*v.z + v.w*v.w;
        atomicAdd(&sred[cl*8 + cc], s);
        atomicAdd(&sred[CH + cl*8 + cc], q);
    }
    __syncthreads();
    if (t < 2*CH) atomicAdd(&g_stats2[t], sred[t]);
}

// ---------------------------------------------------------------- K5: finalize bn2
__global__ void k_bn2(const float* __restrict__ gamma, const float* __restrict__ beta) {
    int c = threadIdx.x;
    if (c >= CH) return;
    const float n = (float)NPIX;
    float mean = g_stats2[c] / n;
    float var  = g_stats2[CH + c] / n - mean*mean;
    float sc = gamma[c] * rsqrtf(var + 1e-3f);
    g_bn2[c]      = sc;
    g_bn2[CH + c] = beta[c] - mean*sc;
}

// ---------------------------------------------------------------- K6: bn2 affine + PReLU
__global__ __launch_bounds__(256) void k_apply(const float* __restrict__ alpha,
                                               float* __restrict__ out) {
    const int n4 = BB*CH*HWS/4;
    int i = blockIdx.x * 256 + threadIdx.x;
    if (i >= n4) return;
    int c = (i / (HWS/4)) % CH;       // HWS divisible by 4 -> channel constant per float4
    float sc = g_bn2[c], sh = g_bn2[CH + c], al = alpha[c];
    float4 v = ((const float4*)g_out0)[i];
    float u;
    u = fmaf(v.x, sc, sh); v.x = u > 0.f ? u : al*u;
    u = fmaf(v.y, sc, sh); v.y = u > 0.f ? u : al*u;
    u = fmaf(v.z, sc, sh); v.z = u > 0.f ? u : al*u;
    u = fmaf(v.w, sc, sh); v.w = u > 0.f ? u : al*u;
    ((float4*)out)[i] = v;
}

// ----------------------------------------------------------------
extern "C" void kernel_launch(void* const* d_in, const int* in_sizes, int n_in,
                              void* d_out, int out_size) {
    const float* x     = (const float*)d_in[0];
    const float* wred  = (const float*)d_in[1];
    const float* g1    = (const float*)d_in[2];
    const float* b1    = (const float*)d_in[3];
    const float* wspan = (const float*)d_in[4];
    const float* g2    = (const float*)d_in[5];
    const float* b2    = (const float*)d_in[6];
    const float* alpha = (const float*)d_in[7];
    float* out = (float*)d_out;

    k_zero  <<<1, 128>>>();
    k_reduce<<<dim3(HWS/128, BB), 128>>>(x, wred);
    k_bn1   <<<1, 64>>>(g1, b1);
    k_span  <<<dim3(HWS/128, BB), 224>>>(wspan);
    k_invol <<<dim3(HH, BB), 224>>>(x);
    k_bn2   <<<1, 64>>>(g2, b2);
    k_apply <<<(BB*CH*HWS/4 + 255)/256, 256>>>(alpha, out);
}

// round 2
// speedup vs baseline: 1.8383x; 1.8383x over previous
#include <cuda_runtime.h>

#define CH   64
#define HH   112
#define WW   112
#define HWS  12544
#define BB   4
#define KK   49
#define NPIX (BB*HWS)

// Scratch (device globals — no allocation allowed)
__device__ __align__(16) float g_y0  [BB*CH*HWS];   // reduce output (pre-BN1)
__device__ __align__(16) float g_out0[BB*CH*HWS];   // involution output (pre-BN2)
__device__ float g_stats1[2*CH];
__device__ float g_stats2[2*CH];

// ---------------------------------------------------------------- K0: zero stats
__global__ void k_zero() {
    int t = threadIdx.x;
    if (t < 2*CH) { g_stats1[t] = 0.f; g_stats2[t] = 0.f; }
}

// ---------------------------------------------------------------- K1: reduce GEMM + stats1
// y0[b,o,p] = sum_c wred[o,c]*x[b,c,p]. Block: 128 pixels, 256 threads.
// Thread tile: 8 outputs x 4 pixels.
__global__ __launch_bounds__(256) void k_reduce(const float* __restrict__ x,
                                                const float* __restrict__ wred) {
    __shared__ __align__(16) float xs[CH][128];
    __shared__ float ws[CH][CH];
    const int t = threadIdx.x;
    const int b = blockIdx.y;
    const int pix0 = blockIdx.x * 128;

    const float* xb = x + (size_t)b*CH*HWS + pix0;
    for (int l = t; l < CH*128; l += 256) {
        int c = l >> 7, p = l & 127;
        xs[c][p] = xb[(size_t)c*HWS + p];
    }
    for (int l = t; l < CH*CH; l += 256) ws[l >> 6][l & 63] = wred[l];
    __syncthreads();

    const int og = t >> 5;     // 8 groups of 8 output channels
    const int pg = t & 31;     // 32 float4 pixel groups
    float acc[8][4];
    #pragma unroll
    for (int i = 0; i < 8; i++)
        #pragma unroll
        for (int j = 0; j < 4; j++) acc[i][j] = 0.f;

    #pragma unroll 4
    for (int c = 0; c < CH; c++) {
        float4 xv = ((const float4*)xs[c])[pg];
        #pragma unroll
        for (int i = 0; i < 8; i++) {
            float w = ws[og*8 + i][c];
            acc[i][0] = fmaf(w, xv.x, acc[i][0]);
            acc[i][1] = fmaf(w, xv.y, acc[i][1]);
            acc[i][2] = fmaf(w, xv.z, acc[i][2]);
            acc[i][3] = fmaf(w, xv.w, acc[i][3]);
        }
    }

    float* y0b = g_y0 + (size_t)b*CH*HWS + pix0;
    #pragma unroll
    for (int i = 0; i < 8; i++) {
        const int o = og*8 + i;
        float4 v; v.x = acc[i][0]; v.y = acc[i][1]; v.z = acc[i][2]; v.w = acc[i][3];
        ((float4*)(y0b + (size_t)o*HWS))[pg] = v;
        float s = v.x + v.y + v.z + v.w;
        float q = v.x*v.x + v.y*v.y + v.z*v.z + v.w*v.w;
        #pragma unroll
        for (int off = 16; off; off >>= 1) {
            s += __shfl_down_sync(0xffffffffu, s, off);
            q += __shfl_down_sync(0xffffffffu, q, off);
        }
        if (pg == 0) {
            atomicAdd(&g_stats1[o], s);
            atomicAdd(&g_stats1[CH + o], q);
        }
    }
}

// ---------------------------------------------------------------- K2: fused bn1 + span GEMM + involution + stats2
// Block: 128 contiguous pixels of one image, 256 threads. Per-pixel kernels
// never leave shared memory.
__global__ __launch_bounds__(256, 3) void k_main(const float* __restrict__ x,
                                                 const float* __restrict__ wspan,
                                                 const float* __restrict__ g1,
                                                 const float* __restrict__ b1) {
    extern __shared__ __align__(16) float sm[];
    float* ws   = sm;                       // [49*64]  span weights
    float* ys   = ws + KK*CH;               // [64*128] bn1-relu'd y0 tile
    float* ks   = ys + CH*128;              // [49*128] per-pixel kernels
    float* bn   = ks + KK*128;              // [128]    bn1 scale/shift
    float* sred = bn + 128;                 // [128]    stats2 partial

    const int t = threadIdx.x;
    const int b = blockIdx.y;
    const int pix0 = blockIdx.x * 128;

    if (t < CH) {
        const float n = (float)NPIX;
        float mean = g_stats1[t] / n;
        float var  = g_stats1[CH + t] / n - mean*mean;
        float sc = g1[t] * rsqrtf(var + 1e-5f);
        bn[t]      = sc;
        bn[CH + t] = b1[t] - mean*sc;
    }
    if (t < 128) sred[t] = 0.f;
    for (int l = t; l < KK*CH; l += 256) ws[l] = wspan[l];
    __syncthreads();

    const float* y0b = g_y0 + (size_t)b*CH*HWS + pix0;
    for (int l = t; l < CH*128; l += 256) {
        int c = l >> 7, p = l & 127;
        float v = y0b[(size_t)c*HWS + p];
        ys[l] = fmaxf(fmaf(v, bn[c], bn[CH + c]), 0.f);
    }
    __syncthreads();

    // ---- span GEMM: kern[p][pix] = sum_c ws[p][c]*ys[c][pix], warps 0..6 ----
    {
        const int og = t >> 5;
        const int pg = t & 31;
        if (og < 7) {
            float acc[7][4];
            #pragma unroll
            for (int i = 0; i < 7; i++)
                #pragma unroll
                for (int j = 0; j < 4; j++) acc[i][j] = 0.f;
            #pragma unroll 4
            for (int c = 0; c < CH; c++) {
                float4 xv = ((const float4*)(ys + c*128))[pg];
                #pragma unroll
                for (int i = 0; i < 7; i++) {
                    float w = ws[(og*7 + i)*CH + c];
                    acc[i][0] = fmaf(w, xv.x, acc[i][0]);
                    acc[i][1] = fmaf(w, xv.y, acc[i][1]);
                    acc[i][2] = fmaf(w, xv.z, acc[i][2]);
                    acc[i][3] = fmaf(w, xv.w, acc[i][3]);
                }
            }
            #pragma unroll
            for (int i = 0; i < 7; i++) {
                float4 v; v.x = acc[i][0]; v.y = acc[i][1]; v.z = acc[i][2]; v.w = acc[i][3];
                ((float4*)(ks + (og*7 + i)*128))[pg] = v;
            }
        }
    }
    __syncthreads();

    // ---- involution: out0[c][pix] = sum_{kh,kw} x[c][h+kh-3][w+kw-3]*ks[kh*7+kw][pix] ----
    {
        const int wg = t & 31;          // pixel float4 group 0..31
        const int cl = t >> 5;          // channel lane: channels cl*8 .. cl*8+7
        const int pp = pix0 + wg*4;     // linear pixel within image
        const int h  = pp / WW;
        const int w0 = pp - h*WW;       // multiple of 4

        float acc[8][4];
        #pragma unroll
        for (int cc = 0; cc < 8; cc++)
            #pragma unroll
            for (int j = 0; j < 4; j++) acc[cc][j] = 0.f;

        const float* xbase = x + ((size_t)b*CH + cl*8)*HWS;
        const float4 zero4 = make_float4(0.f, 0.f, 0.f, 0.f);

        #pragma unroll
        for (int kh = 0; kh < 7; kh++) {
            const int row = h + kh - 3;
            if (row < 0 || row >= HH) continue;
            float4 kv[7];
            #pragma unroll
            for (int kw = 0; kw < 7; kw++)
                kv[kw] = ((const float4*)(ks + (kh*7 + kw)*128))[wg];
            const float* xrow = xbase + (size_t)row*WW;
            #pragma unroll
            for (int cc = 0; cc < 8; cc++) {
                const float* xc = xrow + (size_t)cc*HWS;
                float4 v1 = *(const float4*)(xc + w0);
                float4 v0 = (w0 >= 4)   ? *(const float4*)(xc + w0 - 4) : zero4;
                float4 v2 = (w0 <= 104) ? *(const float4*)(xc + w0 + 4) : zero4;
                float xr[10] = {v0.y, v0.z, v0.w, v1.x, v1.y, v1.z, v1.w, v2.x, v2.y, v2.z};
                #pragma unroll
                for (int kw = 0; kw < 7; kw++) {
                    acc[cc][0] = fmaf(xr[0 + kw], kv[kw].x, acc[cc][0]);
                    acc[cc][1] = fmaf(xr[1 + kw], kv[kw].y, acc[cc][1]);
                    acc[cc][2] = fmaf(xr[2 + kw], kv[kw].z, acc[cc][2]);
                    acc[cc][3] = fmaf(xr[3 + kw], kv[kw].w, acc[cc][3]);
                }
            }
        }

        float* ob = g_out0 + ((size_t)b*CH + cl*8)*HWS + pp;
        #pragma unroll
        for (int cc = 0; cc < 8; cc++) {
            float4 v; v.x = acc[cc][0]; v.y = acc[cc][1]; v.z = acc[cc][2]; v.w = acc[cc][3];
            *((float4*)(ob + (size_t)cc*HWS)) = v;
            float s = v.x + v.y + v.z + v.w;
            float q = v.x*v.x + v.y*v.y + v.z*v.z + v.w*v.w;
            #pragma unroll
            for (int off = 16; off; off >>= 1) {
                s += __shfl_down_sync(0xffffffffu, s, off);
                q += __shfl_down_sync(0xffffffffu, q, off);
            }
            if (wg == 0) {
                atomicAdd(&sred[cl*8 + cc], s);
                atomicAdd(&sred[CH + cl*8 + cc], q);
            }
        }
    }
    __syncthreads();
    if (t < 128) atomicAdd(&g_stats2[t], sred[t]);
}

// ---------------------------------------------------------------- K3: bn2 finalize + affine + PReLU
__global__ __launch_bounds__(256) void k_apply(const float* __restrict__ gamma,
                                               const float* __restrict__ beta,
                                               const float* __restrict__ alpha,
                                               float* __restrict__ out) {
    __shared__ float ssc[CH], ssh[CH], sal[CH];
    const int t = threadIdx.x;
    if (t < CH) {
        const float n = (float)NPIX;
        float mean = g_stats2[t] / n;
        float var  = g_stats2[CH + t] / n - mean*mean;
        float s = gamma[t] * rsqrtf(var + 1e-3f);
        ssc[t] = s;
        ssh[t] = beta[t] - mean*s;
        sal[t] = alpha[t];
    }
    __syncthreads();
    int i = blockIdx.x * 256 + t;                 // grid sized exactly: n4 = 200704
    int c = (i / (HWS/4)) & (CH-1);
    float sc = ssc[c], sh = ssh[c], al = sal[c];
    float4 v = ((const float4*)g_out0)[i];
    float u;
    u = fmaf(v.x, sc, sh); v.x = u > 0.f ? u : al*u;
    u = fmaf(v.y, sc, sh); v.y = u > 0.f ? u : al*u;
    u = fmaf(v.z, sc, sh); v.z = u > 0.f ? u : al*u;
    u = fmaf(v.w, sc, sh); v.w = u > 0.f ? u : al*u;
    ((float4*)out)[i] = v;
}

// ----------------------------------------------------------------
extern "C" void kernel_launch(void* const* d_in, const int* in_sizes, int n_in,
                              void* d_out, int out_size) {
    const float* x     = (const float*)d_in[0];
    const float* wred  = (const float*)d_in[1];
    const float* g1    = (const float*)d_in[2];
    const float* b1    = (const float*)d_in[3];
    const float* wspan = (const float*)d_in[4];
    const float* g2    = (const float*)d_in[5];
    const float* b2    = (const float*)d_in[6];
    const float* alpha = (const float*)d_in[7];
    float* out = (float*)d_out;

    const int smem_main = (KK*CH + CH*128 + KK*128 + 128 + 128) * sizeof(float); // 71424B
    cudaFuncSetAttribute(k_main, cudaFuncAttributeMaxDynamicSharedMemorySize, smem_main);

    k_zero  <<<1, 128>>>();
    k_reduce<<<dim3(HWS/128, BB), 256>>>(x, wred);
    k_main  <<<dim3(HWS/128, BB), 256, smem_main>>>(x, wspan, g1, b1);
    k_apply <<<BB*CH*HWS/4/256, 256>>>(g2, b2, alpha, out);
}